// round 4
// baseline (speedup 1.0000x reference)
#include <cuda_runtime.h>

#define NND 100000
#define NE  1000000

// ---------------- device scratch (static, allocation-free) ----------------
__device__ float g_agg1[(size_t)NND * 64];   // layer-1 neighbor sum of x
__device__ float g_agg2[(size_t)NND * 64];   // layer-2 neighbor sum of p
__device__ float g_h   [(size_t)NND * 128];  // hidden activations
__device__ float g_p   [(size_t)NND * 64];   // h @ W2l (pre-aggregation)
__device__ float g_rinv[NND];                // 1 / max(cnt,1)
__device__ int   g_cnt [NND];
__device__ int   g_src [NE];
__device__ int   g_dst [NE];

// ---------------- init: zero accumulators, copy+clamp int32 edges ----------------
__global__ void k_init(const int* __restrict__ ei) {
    int i = blockIdx.x * 256 + threadIdx.x;          // exactly NND*64 = 6.4M threads
    g_agg1[i] = 0.f;
    g_agg2[i] = 0.f;
    if (i < NND) g_cnt[i] = 0;
    if (i < NE) {
        int s = ei[i];
        int d = ei[NE + i];
        g_src[i] = (s < 0) ? 0 : (s >= NND ? NND - 1 : s);
        g_dst[i] = (d < 0) ? 0 : (d >= NND ? NND - 1 : d);
    }
}

// ---------------- scatter: agg[dst] += feat[src] (64 floats/edge) ----------------
template <int LAYER>
__global__ void k_scatter(const float* __restrict__ xin) {
    int t = blockIdx.x * 256 + threadIdx.x;          // exactly NE*16 = 16M threads
    int e = t >> 4;
    int c = t & 15;
    int s = g_src[e];
    int d = g_dst[e];
    const float* feat = (LAYER == 1) ? xin : g_p;
    float*       agg  = (LAYER == 1) ? g_agg1 : g_agg2;
    float4 v = __ldg((const float4*)feat + (size_t)s * 16 + c);
    float* a = agg + (size_t)d * 64 + (c << 2);
    asm volatile("red.global.add.v4.f32 [%0], {%1,%2,%3,%4};"
                 :: "l"(a), "f"(v.x), "f"(v.y), "f"(v.z), "f"(v.w) : "memory");
    if (LAYER == 1 && c == 0) atomicAdd(&g_cnt[d], 1);
}

// ---------------- unified 64x128x128 GEMM ----------------
// MODE 1: h = relu( concat(agg1*rinv [64], x [64]) @ [W1l ; W1r] + b1 ), out 128 wide.
// MODE 2: [p | out] = h @ [W2l | W2r], left no bias -> g_p, right + b2 -> out.
// 128 threads/block, tile 64 nodes x 128 cols, 8 nodes x 8 cols per thread.
extern __shared__ float sm[];

template <int MODE>
__global__ __launch_bounds__(128, 4)
void k_gemm(const float* __restrict__ xin, const float* __restrict__ Wa,
            const float* __restrict__ Wb, const float* __restrict__ bias,
            float* __restrict__ outr) {
    float* Ws = sm;                 // 128 x 128
    float* As = sm + 16384;         // 64 x 132 (pad keeps float4 alignment)
    int tid = threadIdx.x;
    int nodeB = blockIdx.x * 64;

    // Stage weights (128x128 = 4096 float4)
    for (int j = tid; j < 4096; j += 128) {
        float4 v;
        if (MODE == 1) {            // stacked: rows 0-63 = W1l, 64-127 = W1r
            v = (j < 2048) ? __ldg((const float4*)Wa + j)
                           : __ldg((const float4*)Wb + (j - 2048));
        } else {                    // side-by-side: cols 0-63 = W2l, 64-127 = W2r
            int k = j >> 5, c4 = j & 31;
            v = (c4 < 16) ? __ldg((const float4*)Wa + k * 16 + c4)
                          : __ldg((const float4*)Wb + k * 16 + (c4 - 16));
        }
        ((float4*)Ws)[j] = v;
    }

    // Stage A (64 nodes x 32 float4)
    for (int i = tid; i < 2048; i += 128) {
        int n = i >> 5, f = i & 31;
        int node = nodeB + n;
        float4 v = make_float4(0.f, 0.f, 0.f, 0.f);
        if (node < NND) {
            if (MODE == 1) {
                if (f < 16) {       // k 0..63 : mean = agg1 * rinv
                    v = *((const float4*)g_agg1 + (size_t)node * 16 + f);
                    int cn = g_cnt[node];
                    float ri = 1.f / (float)(cn < 1 ? 1 : cn);
                    v.x *= ri; v.y *= ri; v.z *= ri; v.w *= ri;
                    if (f == 0) g_rinv[node] = ri;
                } else {            // k 64..127 : x
                    v = __ldg((const float4*)xin + (size_t)node * 16 + (f - 16));
                }
            } else {
                v = *((const float4*)g_h + (size_t)node * 32 + f);
            }
        }
        ((float4*)(As + n * 132))[f] = v;
    }
    __syncthreads();

    int cg = tid & 15;              // col group -> cols cg*8..+7 (of 128)
    int ng = tid >> 4;              // node group -> nodes ng*8..+7
    int c0 = cg * 8;
    int n0 = ng * 8;

    float bv[8];
    #pragma unroll
    for (int q = 0; q < 8; q++) {
        if (MODE == 1)      bv[q] = __ldg(bias + c0 + q);
        else if (cg >= 8)   bv[q] = __ldg(bias + (c0 - 64) + q);
        else                bv[q] = 0.f;
    }
    float acc[8][8];
    #pragma unroll
    for (int j = 0; j < 8; j++)
        #pragma unroll
        for (int q = 0; q < 8; q++) acc[j][q] = bv[q];

    #pragma unroll 4
    for (int k = 0; k < 128; k++) {
        float4 w0 = *(const float4*)(Ws + k * 128 + c0);
        float4 w1 = *(const float4*)(Ws + k * 128 + c0 + 4);
        float a[8];
        #pragma unroll
        for (int j = 0; j < 8; j++) a[j] = As[(n0 + j) * 132 + k];
        #pragma unroll
        for (int j = 0; j < 8; j++) {
            acc[j][0] = fmaf(a[j], w0.x, acc[j][0]);
            acc[j][1] = fmaf(a[j], w0.y, acc[j][1]);
            acc[j][2] = fmaf(a[j], w0.z, acc[j][2]);
            acc[j][3] = fmaf(a[j], w0.w, acc[j][3]);
            acc[j][4] = fmaf(a[j], w1.x, acc[j][4]);
            acc[j][5] = fmaf(a[j], w1.y, acc[j][5]);
            acc[j][6] = fmaf(a[j], w1.z, acc[j][6]);
            acc[j][7] = fmaf(a[j], w1.w, acc[j][7]);
        }
    }

    #pragma unroll
    for (int j = 0; j < 8; j++) {
        int node = nodeB + n0 + j;
        if (node < NND) {
            if (MODE == 1) {
                float4 o0 = make_float4(fmaxf(acc[j][0],0.f), fmaxf(acc[j][1],0.f),
                                        fmaxf(acc[j][2],0.f), fmaxf(acc[j][3],0.f));
                float4 o1 = make_float4(fmaxf(acc[j][4],0.f), fmaxf(acc[j][5],0.f),
                                        fmaxf(acc[j][6],0.f), fmaxf(acc[j][7],0.f));
                float4* dp = (float4*)(g_h + (size_t)node * 128 + c0);
                dp[0] = o0;
                dp[1] = o1;
            } else {
                float* dst = (cg < 8) ? g_p : outr;
                float4* dp = (float4*)(dst + (size_t)node * 64 + (c0 & 63));
                dp[0] = make_float4(acc[j][0], acc[j][1], acc[j][2], acc[j][3]);
                dp[1] = make_float4(acc[j][4], acc[j][5], acc[j][6], acc[j][7]);
            }
        }
    }
}

// ---------------- finalize: out += agg2 * rinv ----------------
__global__ void k_final(float* __restrict__ out) {
    int t = blockIdx.x * 256 + threadIdx.x;     // exactly NND*16 = 1.6M threads
    int node = t >> 4;
    float ri = g_rinv[node];
    float4 a = ((const float4*)g_agg2)[t];
    float4 o = ((float4*)out)[t];
    o.x = fmaf(a.x, ri, o.x);
    o.y = fmaf(a.y, ri, o.y);
    o.z = fmaf(a.z, ri, o.z);
    o.w = fmaf(a.w, ri, o.w);
    ((float4*)out)[t] = o;
}

// ---------------- launch ----------------
extern "C" void kernel_launch(void* const* d_in, const int* in_sizes, int n_in,
                              void* d_out, int out_size) {
    const float* x   = nullptr;
    const float* b1  = nullptr;
    const float* b2  = nullptr;
    const int*   ei  = nullptr;
    const float* W[4] = {nullptr, nullptr, nullptr, nullptr};
    int wn = 0;
    for (int i = 0; i < n_in; i++) {
        int sz = in_sizes[i];
        if      (sz == NND * 64)  x  = (const float*)d_in[i];
        else if (sz == 2 * NE)    ei = (const int*)d_in[i];
        else if (sz == 128)       b1 = (const float*)d_in[i];
        else if (sz == 64)        b2 = (const float*)d_in[i];
        else if (sz == 8192 && wn < 4) W[wn++] = (const float*)d_in[i];
    }
    const float* W1l = W[0];
    const float* W1r = W[1];
    const float* W2l = W[2];
    const float* W2r = W[3];
    float* out = (float*)d_out;

    const int SMG = (16384 + 64 * 132) * 4;      // 99328 B
    cudaFuncSetAttribute(k_gemm<1>, cudaFuncAttributeMaxDynamicSharedMemorySize, SMG);
    cudaFuncSetAttribute(k_gemm<2>, cudaFuncAttributeMaxDynamicSharedMemorySize, SMG);

    int gemm_blocks = (NND + 63) / 64;           // 1563

    k_init<<<25000, 256>>>(ei);                  // NND*64 threads
    k_scatter<1><<<62500, 256>>>(x);             // NE*16 threads, also counts degrees
    k_gemm<1><<<gemm_blocks, 128, SMG>>>(x, W1l, W1r, b1, nullptr);
    k_gemm<2><<<gemm_blocks, 128, SMG>>>(nullptr, W2l, W2r, b2, out);
    k_scatter<2><<<62500, 256>>>(nullptr);       // p -> agg2
    k_final<<<6250, 256>>>(out);                 // NND*16 threads
}

// round 5
// speedup vs baseline: 1.7076x; 1.7076x over previous
#include <cuda_runtime.h>

#define NND 100000
#define NE  1000000

// ---------------- device scratch (static, allocation-free) ----------------
__device__ float g_agg1[(size_t)NND * 64];   // layer-1 neighbor sum of x
__device__ float g_agg2[(size_t)NND * 64];   // layer-2 neighbor sum of p
__device__ float g_h   [(size_t)NND * 128];  // hidden activations
__device__ float g_p   [(size_t)NND * 64];   // h @ W2l (pre-aggregation)
__device__ float g_rinv[NND];                // 1 / max(cnt,1)
__device__ int   g_cnt [NND];
__device__ int   g_src [NE];
__device__ int   g_dst [NE];

// ---------------- f32x2 helpers (sm_103a packed fp32 SIMD) ----------------
__device__ __forceinline__ unsigned long long pk2(float lo, float hi) {
    unsigned long long r;
    asm("mov.b64 %0, {%1, %2};" : "=l"(r) : "f"(lo), "f"(hi));
    return r;
}
__device__ __forceinline__ void upk2(float& lo, float& hi, unsigned long long v) {
    asm("mov.b64 {%0, %1}, %2;" : "=f"(lo), "=f"(hi) : "l"(v));
}
#define FMA2(d, a, b) \
    asm("fma.rn.f32x2 %0, %1, %2, %0;" : "+l"(d) : "l"(a), "l"(b))

// ---------------- init: zero accumulators, copy+clamp int32 edges ----------------
__global__ void k_init(const int* __restrict__ ei) {
    int i = blockIdx.x * 256 + threadIdx.x;          // exactly NND*64 = 6.4M threads
    g_agg1[i] = 0.f;
    g_agg2[i] = 0.f;
    if (i < NND) g_cnt[i] = 0;
    if (i < NE) {
        int s = ei[i];
        int d = ei[NE + i];
        g_src[i] = (s < 0) ? 0 : (s >= NND ? NND - 1 : s);
        g_dst[i] = (d < 0) ? 0 : (d >= NND ? NND - 1 : d);
    }
}

// ---------------- scatter: agg[dst] += feat[src] (64 floats/edge) ----------------
template <int LAYER>
__global__ void k_scatter(const float* __restrict__ xin) {
    int t = blockIdx.x * 256 + threadIdx.x;          // exactly NE*16 = 16M threads
    int e = t >> 4;
    int c = t & 15;
    int s = g_src[e];
    int d = g_dst[e];
    const float* feat = (LAYER == 1) ? xin : g_p;
    float*       agg  = (LAYER == 1) ? g_agg1 : g_agg2;
    float4 v = __ldg((const float4*)feat + (size_t)s * 16 + c);
    float* a = agg + (size_t)d * 64 + (c << 2);
    asm volatile("red.global.add.v4.f32 [%0], {%1,%2,%3,%4};"
                 :: "l"(a), "f"(v.x), "f"(v.y), "f"(v.z), "f"(v.w) : "memory");
    if (LAYER == 1 && c == 0) atomicAdd(&g_cnt[d], 1);
}

// ---------------- unified 64x128x128 GEMM, f32x2 packed ----------------
// MODE 1: h = relu( concat(agg1*rinv, x) @ [W1l ; W1r] + b1 )
// MODE 2: [p | out] = h @ [W2l | W2r]  (right half + b2 -> out)
// 256 threads: cg = tid&31 (4 cols), ng = tid>>5 (8 nodes).
// Warp spans all 32 col-groups (W LDS.128 conflict-free) and ONE node-group
// (A loads are broadcast). 8n x 4c = 16 f32x2 accumulators per thread.
extern __shared__ float sm[];

template <int MODE>
__global__ __launch_bounds__(256, 2)
void k_gemm(const float* __restrict__ xin, const float* __restrict__ Wa,
            const float* __restrict__ Wb, const float* __restrict__ bias,
            float* __restrict__ outr) {
    float* Ws = sm;                 // 128 x 128 (merged)
    float* As = sm + 16384;         // 64 x 132 (padded)
    int tid = threadIdx.x;
    int nodeB = blockIdx.x * 64;

    // Stage weights (128x128 = 4096 float4)
    for (int j = tid; j < 4096; j += 256) {
        float4 v;
        if (MODE == 1) {            // stacked: rows 0-63 = W1l, 64-127 = W1r
            v = (j < 2048) ? __ldg((const float4*)Wa + j)
                           : __ldg((const float4*)Wb + (j - 2048));
        } else {                    // side-by-side: cols 0-63 = W2l, 64-127 = W2r
            int k = j >> 5, c4 = j & 31;
            v = (c4 < 16) ? __ldg((const float4*)Wa + k * 16 + c4)
                          : __ldg((const float4*)Wb + k * 16 + (c4 - 16));
        }
        ((float4*)Ws)[j] = v;
    }

    // Stage A (64 nodes x 32 float4)
    for (int i = tid; i < 2048; i += 256) {
        int n = i >> 5, f = i & 31;
        int node = nodeB + n;
        float4 v = make_float4(0.f, 0.f, 0.f, 0.f);
        if (node < NND) {
            if (MODE == 1) {
                if (f < 16) {       // k 0..63 : mean = agg1 * rinv
                    v = *((const float4*)g_agg1 + (size_t)node * 16 + f);
                    int cn = g_cnt[node];
                    float ri = 1.f / (float)(cn < 1 ? 1 : cn);
                    v.x *= ri; v.y *= ri; v.z *= ri; v.w *= ri;
                    if (f == 0) g_rinv[node] = ri;
                } else {            // k 64..127 : x
                    v = __ldg((const float4*)xin + (size_t)node * 16 + (f - 16));
                }
            } else {
                v = *((const float4*)g_h + (size_t)node * 32 + f);
            }
        }
        ((float4*)(As + n * 132))[f] = v;
    }
    __syncthreads();

    int cg = tid & 31;              // col group -> cols cg*4..+3 (of 128)
    int ng = tid >> 5;              // node group -> nodes ng*8..+7
    int c0 = cg * 4;
    int n0 = ng * 8;

    float bv[4];
    #pragma unroll
    for (int q = 0; q < 4; q++) {
        if (MODE == 1)      bv[q] = __ldg(bias + c0 + q);
        else if (cg >= 16)  bv[q] = __ldg(bias + (c0 - 64) + q);
        else                bv[q] = 0.f;
    }
    unsigned long long acc[8][2];
    #pragma unroll
    for (int j = 0; j < 8; j++) {
        acc[j][0] = pk2(bv[0], bv[1]);
        acc[j][1] = pk2(bv[2], bv[3]);
    }

    #pragma unroll 2
    for (int k4 = 0; k4 < 32; k4++) {
        float4 av[8];
        #pragma unroll
        for (int j = 0; j < 8; j++)
            av[j] = *(const float4*)(As + (n0 + j) * 132 + k4 * 4);
        #pragma unroll
        for (int kk = 0; kk < 4; kk++) {
            float4 w = *(const float4*)(Ws + (k4 * 4 + kk) * 128 + c0);
            unsigned long long w01 = pk2(w.x, w.y);
            unsigned long long w23 = pk2(w.z, w.w);
            #pragma unroll
            for (int j = 0; j < 8; j++) {
                float a = (kk == 0) ? av[j].x : (kk == 1) ? av[j].y
                        : (kk == 2) ? av[j].z : av[j].w;
                unsigned long long aa = pk2(a, a);
                FMA2(acc[j][0], aa, w01);
                FMA2(acc[j][1], aa, w23);
            }
        }
    }

    #pragma unroll
    for (int j = 0; j < 8; j++) {
        int node = nodeB + n0 + j;
        if (node < NND) {
            float f0, f1, f2, f3;
            upk2(f0, f1, acc[j][0]);
            upk2(f2, f3, acc[j][1]);
            if (MODE == 1) {
                *(float4*)(g_h + (size_t)node * 128 + c0) =
                    make_float4(fmaxf(f0,0.f), fmaxf(f1,0.f),
                                fmaxf(f2,0.f), fmaxf(f3,0.f));
            } else {
                float* dst = (cg < 16) ? g_p : outr;
                int col = (cg < 16) ? c0 : (c0 - 64);
                *(float4*)(dst + (size_t)node * 64 + col) =
                    make_float4(f0, f1, f2, f3);
            }
        }
    }
}

// ---------------- finalize: out += agg2 * rinv ----------------
__global__ void k_final(float* __restrict__ out) {
    int t = blockIdx.x * 256 + threadIdx.x;     // exactly NND*16 = 1.6M threads
    int node = t >> 4;
    float ri = g_rinv[node];
    float4 a = ((const float4*)g_agg2)[t];
    float4 o = ((float4*)out)[t];
    o.x = fmaf(a.x, ri, o.x);
    o.y = fmaf(a.y, ri, o.y);
    o.z = fmaf(a.z, ri, o.z);
    o.w = fmaf(a.w, ri, o.w);
    ((float4*)out)[t] = o;
}

// ---------------- launch ----------------
extern "C" void kernel_launch(void* const* d_in, const int* in_sizes, int n_in,
                              void* d_out, int out_size) {
    const float* x   = nullptr;
    const float* b1  = nullptr;
    const float* b2  = nullptr;
    const int*   ei  = nullptr;
    const float* W[4] = {nullptr, nullptr, nullptr, nullptr};
    int wn = 0;
    for (int i = 0; i < n_in; i++) {
        int sz = in_sizes[i];
        if      (sz == NND * 64)  x  = (const float*)d_in[i];
        else if (sz == 2 * NE)    ei = (const int*)d_in[i];
        else if (sz == 128)       b1 = (const float*)d_in[i];
        else if (sz == 64)        b2 = (const float*)d_in[i];
        else if (sz == 8192 && wn < 4) W[wn++] = (const float*)d_in[i];
    }
    const float* W1l = W[0];
    const float* W1r = W[1];
    const float* W2l = W[2];
    const float* W2r = W[3];
    float* out = (float*)d_out;

    const int SMG = (16384 + 64 * 132) * 4;      // 99328 B
    cudaFuncSetAttribute(k_gemm<1>, cudaFuncAttributeMaxDynamicSharedMemorySize, SMG);
    cudaFuncSetAttribute(k_gemm<2>, cudaFuncAttributeMaxDynamicSharedMemorySize, SMG);

    int gemm_blocks = (NND + 63) / 64;           // 1563

    k_init<<<25000, 256>>>(ei);                  // NND*64 threads
    k_scatter<1><<<62500, 256>>>(x);             // NE*16 threads, also counts degrees
    k_gemm<1><<<gemm_blocks, 256, SMG>>>(x, W1l, W1r, b1, nullptr);
    k_gemm<2><<<gemm_blocks, 256, SMG>>>(nullptr, W2l, W2r, b2, out);
    k_scatter<2><<<62500, 256>>>(nullptr);       // p -> agg2
    k_final<<<6250, 256>>>(out);                 // NND*16 threads
}

// round 6
// speedup vs baseline: 1.7638x; 1.0330x over previous
#include <cuda_runtime.h>

#define NND 100000
#define NE  1000000

// ---------------- device scratch (static, allocation-free) ----------------
__device__ float g_agg1[(size_t)NND * 64];   // layer-1 neighbor sum of x
__device__ float g_agg2[(size_t)NND * 64];   // layer-2 neighbor sum of p
__device__ float g_h   [(size_t)NND * 128];  // hidden activations
__device__ float g_p   [(size_t)NND * 64];   // h @ W2l (pre-aggregation)
__device__ float g_rinv[NND];                // 1 / max(cnt,1)
__device__ int   g_cnt [NND];
__device__ int   g_src [NE];
__device__ int   g_dst [NE];

// ---------------- f32x2 helpers (sm_103a packed fp32 SIMD) ----------------
__device__ __forceinline__ unsigned long long pk2(float lo, float hi) {
    unsigned long long r;
    asm("mov.b64 %0, {%1, %2};" : "=l"(r) : "f"(lo), "f"(hi));
    return r;
}
__device__ __forceinline__ void upk2(float& lo, float& hi, unsigned long long v) {
    asm("mov.b64 {%0, %1}, %2;" : "=f"(lo), "=f"(hi) : "l"(v));
}
#define FMA2(d, a, b) \
    asm("fma.rn.f32x2 %0, %1, %2, %0;" : "+l"(d) : "l"(a), "l"(b))

// ---------------- init: zero accumulators, copy+clamp int32 edges ----------------
__global__ void k_init(const int* __restrict__ ei) {
    int i = blockIdx.x * 256 + threadIdx.x;          // exactly NND*64 = 6.4M threads
    g_agg1[i] = 0.f;
    g_agg2[i] = 0.f;
    if (i < NND) g_cnt[i] = 0;
    if (i < NE) {
        int s = ei[i];
        int d = ei[NE + i];
        g_src[i] = (s < 0) ? 0 : (s >= NND ? NND - 1 : s);
        g_dst[i] = (d < 0) ? 0 : (d >= NND ? NND - 1 : d);
    }
}

// ---------------- scatter: agg[dst] += feat[src] (64 floats/edge) ----------------
template <int LAYER>
__global__ void k_scatter(const float* __restrict__ xin) {
    int t = blockIdx.x * 256 + threadIdx.x;          // exactly NE*16 = 16M threads
    int e = t >> 4;
    int c = t & 15;
    int s = g_src[e];
    int d = g_dst[e];
    const float* feat = (LAYER == 1) ? xin : g_p;
    float*       agg  = (LAYER == 1) ? g_agg1 : g_agg2;
    float4 v = __ldg((const float4*)feat + (size_t)s * 16 + c);
    float* a = agg + (size_t)d * 64 + (c << 2);
    asm volatile("red.global.add.v4.f32 [%0], {%1,%2,%3,%4};"
                 :: "l"(a), "f"(v.x), "f"(v.y), "f"(v.z), "f"(v.w) : "memory");
    if (LAYER == 1 && c == 0) atomicAdd(&g_cnt[d], 1);
}

// ---------------- unified GEMM, col-split for occupancy ----------------
// Tile: 64 nodes x 64 cols (blockIdx.y = column half of the 128-wide output).
// MODE 1: h[:, half] = relu( concat(agg1*rinv, x) @ [W1l;W1r][:, half] + b1[half] )
// MODE 2: half 0 -> g_p = h @ W2l ; half 1 -> out = h @ W2r + b2
// 256 threads: cg = tid&15 (4 cols), ng = tid>>4 (4 nodes). 4n x 4c = 8 FMA2/thread/k.
// Smem = 32KB W + 32KB A = 64KB -> 3 blocks/SM (24 warps).
extern __shared__ float sm[];

template <int MODE>
__global__ __launch_bounds__(256, 3)
void k_gemm(const float* __restrict__ xin, const float* __restrict__ Wa,
            const float* __restrict__ Wb, const float* __restrict__ bias,
            float* __restrict__ outr) {
    float* Ws = sm;                 // 128 k x 64 cols
    float* As = sm + 8192;          // 64 nodes x 128 k
    int tid = threadIdx.x;
    int nodeB = blockIdx.x * 64;
    int h = blockIdx.y;             // column half: 0 or 1

    // Stage weights: 128 x 16 float4
    for (int j = tid; j < 2048; j += 256) {
        float4 v;
        if (MODE == 1) {            // stacked rows: 0-63 W1l, 64-127 W1r; cols h*64..
            int r = j >> 4, c4 = j & 15;
            const float* W = (r < 64) ? Wa : Wb;
            v = __ldg((const float4*)W + (r & 63) * 32 + h * 16 + c4);
        } else {                    // half 0 = W2l, half 1 = W2r (each 128x64)
            v = __ldg((const float4*)(h ? Wb : Wa) + j);
        }
        ((float4*)Ws)[j] = v;
    }

    // Stage A: 64 nodes x 32 float4
    for (int i = tid; i < 2048; i += 256) {
        int n = i >> 5, f = i & 31;
        int node = nodeB + n;
        float4 v = make_float4(0.f, 0.f, 0.f, 0.f);
        if (node < NND) {
            if (MODE == 1) {
                if (f < 16) {       // k 0..63 : mean = agg1 * rinv
                    v = *((const float4*)g_agg1 + (size_t)node * 16 + f);
                    int cn = g_cnt[node];
                    float ri = 1.f / (float)(cn < 1 ? 1 : cn);
                    v.x *= ri; v.y *= ri; v.z *= ri; v.w *= ri;
                    if (f == 0 && h == 0) g_rinv[node] = ri;
                } else {            // k 64..127 : x
                    v = __ldg((const float4*)xin + (size_t)node * 16 + (f - 16));
                }
            } else {
                v = *((const float4*)g_h + (size_t)node * 32 + f);
            }
        }
        ((float4*)(As + n * 128))[f] = v;
    }
    __syncthreads();

    int cg = tid & 15;              // col group -> cols cg*4..+3 (of this 64 half)
    int ng = tid >> 4;              // node group -> nodes ng*4..+3
    int c0 = cg * 4;
    int n0 = ng * 4;

    float bv[4];
    #pragma unroll
    for (int q = 0; q < 4; q++) {
        if (MODE == 1)              bv[q] = __ldg(bias + h * 64 + c0 + q);
        else if (h == 1)            bv[q] = __ldg(bias + c0 + q);
        else                        bv[q] = 0.f;
    }
    unsigned long long acc[4][2];
    #pragma unroll
    for (int j = 0; j < 4; j++) {
        acc[j][0] = pk2(bv[0], bv[1]);
        acc[j][1] = pk2(bv[2], bv[3]);
    }

    #pragma unroll 4
    for (int k4 = 0; k4 < 32; k4++) {
        float4 av[4];
        #pragma unroll
        for (int j = 0; j < 4; j++)
            av[j] = *(const float4*)(As + (n0 + j) * 128 + k4 * 4);
        #pragma unroll
        for (int kk = 0; kk < 4; kk++) {
            float4 w = *(const float4*)(Ws + (k4 * 4 + kk) * 64 + c0);
            unsigned long long w01 = pk2(w.x, w.y);
            unsigned long long w23 = pk2(w.z, w.w);
            #pragma unroll
            for (int j = 0; j < 4; j++) {
                float a = (kk == 0) ? av[j].x : (kk == 1) ? av[j].y
                        : (kk == 2) ? av[j].z : av[j].w;
                unsigned long long aa = pk2(a, a);
                FMA2(acc[j][0], aa, w01);
                FMA2(acc[j][1], aa, w23);
            }
        }
    }

    #pragma unroll
    for (int j = 0; j < 4; j++) {
        int node = nodeB + n0 + j;
        if (node < NND) {
            float f0, f1, f2, f3;
            upk2(f0, f1, acc[j][0]);
            upk2(f2, f3, acc[j][1]);
            if (MODE == 1) {
                *(float4*)(g_h + (size_t)node * 128 + h * 64 + c0) =
                    make_float4(fmaxf(f0,0.f), fmaxf(f1,0.f),
                                fmaxf(f2,0.f), fmaxf(f3,0.f));
            } else {
                float* dst = h ? outr : g_p;
                *(float4*)(dst + (size_t)node * 64 + c0) =
                    make_float4(f0, f1, f2, f3);
            }
        }
    }
}

// ---------------- finalize: out += agg2 * rinv ----------------
__global__ void k_final(float* __restrict__ out) {
    int t = blockIdx.x * 256 + threadIdx.x;     // exactly NND*16 = 1.6M threads
    int node = t >> 4;
    float ri = g_rinv[node];
    float4 a = ((const float4*)g_agg2)[t];
    float4 o = ((float4*)out)[t];
    o.x = fmaf(a.x, ri, o.x);
    o.y = fmaf(a.y, ri, o.y);
    o.z = fmaf(a.z, ri, o.z);
    o.w = fmaf(a.w, ri, o.w);
    ((float4*)out)[t] = o;
}

// ---------------- launch ----------------
extern "C" void kernel_launch(void* const* d_in, const int* in_sizes, int n_in,
                              void* d_out, int out_size) {
    const float* x   = nullptr;
    const float* b1  = nullptr;
    const float* b2  = nullptr;
    const int*   ei  = nullptr;
    const float* W[4] = {nullptr, nullptr, nullptr, nullptr};
    int wn = 0;
    for (int i = 0; i < n_in; i++) {
        int sz = in_sizes[i];
        if      (sz == NND * 64)  x  = (const float*)d_in[i];
        else if (sz == 2 * NE)    ei = (const int*)d_in[i];
        else if (sz == 128)       b1 = (const float*)d_in[i];
        else if (sz == 64)        b2 = (const float*)d_in[i];
        else if (sz == 8192 && wn < 4) W[wn++] = (const float*)d_in[i];
    }
    const float* W1l = W[0];
    const float* W1r = W[1];
    const float* W2l = W[2];
    const float* W2r = W[3];
    float* out = (float*)d_out;

    const int SMG = 65536;                        // 32KB W + 32KB A
    cudaFuncSetAttribute(k_gemm<1>, cudaFuncAttributeMaxDynamicSharedMemorySize, SMG);
    cudaFuncSetAttribute(k_gemm<2>, cudaFuncAttributeMaxDynamicSharedMemorySize, SMG);

    dim3 gemm_grid((NND + 63) / 64, 2);          // 1563 x 2

    k_init<<<25000, 256>>>(ei);                  // NND*64 threads
    k_scatter<1><<<62500, 256>>>(x);             // NE*16 threads, also counts degrees
    k_gemm<1><<<gemm_grid, 256, SMG>>>(x, W1l, W1r, b1, nullptr);
    k_gemm<2><<<gemm_grid, 256, SMG>>>(nullptr, W2l, W2r, b2, out);
    k_scatter<2><<<62500, 256>>>(nullptr);       // p -> agg2
    k_final<<<6250, 256>>>(out);                 // NND*16 threads
}

// round 7
// speedup vs baseline: 1.8995x; 1.0769x over previous
#include <cuda_runtime.h>

#define NND 100000
#define NE  1000000

// ---------------- device scratch (static, allocation-free) ----------------
__device__ float g_agg1[(size_t)NND * 64];   // layer-1 neighbor sum of x
__device__ float g_agg2[(size_t)NND * 64];   // layer-2 neighbor sum of p
__device__ float g_h   [(size_t)NND * 128];  // hidden activations
__device__ float g_p   [(size_t)NND * 64];   // h @ W2l (pre-aggregation)
__device__ float g_rinv[NND];                // 1 / max(cnt,1)
__device__ int   g_cnt [NND];
__device__ int   g_src [NE];
__device__ int   g_dst [NE];

// ---------------- f32x2 helpers (sm_103a packed fp32 SIMD) ----------------
__device__ __forceinline__ unsigned long long pk2(float lo, float hi) {
    unsigned long long r;
    asm("mov.b64 %0, {%1, %2};" : "=l"(r) : "f"(lo), "f"(hi));
    return r;
}
__device__ __forceinline__ void upk2(float& lo, float& hi, unsigned long long v) {
    asm("mov.b64 {%0, %1}, %2;" : "=f"(lo), "=f"(hi) : "l"(v));
}
#define FMA2(d, a, b) \
    asm("fma.rn.f32x2 %0, %1, %2, %0;" : "+l"(d) : "l"(a), "l"(b))

// ---------------- init: zero accumulators, copy+clamp int32 edges ----------------
__global__ void k_init(const int* __restrict__ ei) {
    int i = blockIdx.x * 256 + threadIdx.x;          // exactly NND*64 = 6.4M threads
    g_agg1[i] = 0.f;
    g_agg2[i] = 0.f;
    if (i < NND) g_cnt[i] = 0;
    if (i < NE) {
        int s = ei[i];
        int d = ei[NE + i];
        g_src[i] = (s < 0) ? 0 : (s >= NND ? NND - 1 : s);
        g_dst[i] = (d < 0) ? 0 : (d >= NND ? NND - 1 : d);
    }
}

// ---------------- scatter: agg[dst] += feat[src] (64 floats/edge) ----------------
template <int LAYER>
__global__ void k_scatter(const float* __restrict__ xin) {
    int t = blockIdx.x * 256 + threadIdx.x;          // exactly NE*16 = 16M threads
    int e = t >> 4;
    int c = t & 15;
    int s = g_src[e];
    int d = g_dst[e];
    const float* feat = (LAYER == 1) ? xin : g_p;
    float*       agg  = (LAYER == 1) ? g_agg1 : g_agg2;
    float4 v = __ldg((const float4*)feat + (size_t)s * 16 + c);
    float* a = agg + (size_t)d * 64 + (c << 2);
    asm volatile("red.global.add.v4.f32 [%0], {%1,%2,%3,%4};"
                 :: "l"(a), "f"(v.x), "f"(v.y), "f"(v.z), "f"(v.w) : "memory");
    if (LAYER == 1 && c == 0) atomicAdd(&g_cnt[d], 1);
}

// ---------------- unified 128x128x128 GEMM, f32x2, phase-clean layout ----------------
// Tile: 128 nodes x 128 cols, K=128 staged in two 64-chunks.
// MODE 1: h = relu( concat(agg1*rinv, x) @ [W1l;W1r] + b1 )  (chunk0=mean, chunk1=x)
// MODE 2: cols 0-63 -> g_p = h @ W2l ; cols 64-127 -> out = h @ W2r + b2
// 256 threads, bits: cglo=tid[0:2) nglo=tid[2:4) cghi=tid[4:6) nghi=tid[6:8).
// cg = cglo+4*cghi (8 cols each), ng = nglo+4*nghi (nodes ng+16j, j=0..7).
// Per thread 8n x 8c = 32 f32x2 accs. Half-warps cover distinct W/A addresses.
extern __shared__ float sm[];

template <int MODE>
__global__ __launch_bounds__(256, 2)
void k_gemm(const float* __restrict__ xin, const float* __restrict__ Wa,
            const float* __restrict__ Wb, const float* __restrict__ bias,
            float* __restrict__ outr) {
    float* Ws = sm;                  // 128 k x 128 c (floats), stride 128
    float* As = sm + 16384;          // 128 nodes x 17 float4 (chunk of 16 k4)
    int tid = threadIdx.x;
    int nodeB = blockIdx.x * 128;

    // ---- stage W fully (4096 float4) ----
    #pragma unroll
    for (int m = 0; m < 16; m++) {
        int j = tid + 256 * m;
        int k = j >> 5, c4 = j & 31;
        float4 v;
        if (MODE == 1) {             // stacked rows: 0-63 W1l, 64-127 W1r
            v = __ldg((const float4*)(k < 64 ? Wa : Wb) + (k & 63) * 32 + c4);
        } else {                     // side-by-side: cols 0-63 W2l, 64-127 W2r
            v = (c4 < 16) ? __ldg((const float4*)Wa + k * 16 + c4)
                          : __ldg((const float4*)Wb + k * 16 + (c4 - 16));
        }
        ((float4*)Ws)[j] = v;
    }

    int cglo = tid & 3;
    int nglo = (tid >> 2) & 3;
    int cghi = (tid >> 4) & 3;
    int nghi = tid >> 6;
    int cg = cglo + 4 * cghi;        // 0..15 -> cols cg*8..+7
    int ng = nglo + 4 * nghi;        // 0..15 -> nodes ng+16j

    // ---- bias / acc init ----
    float bv[8];
    #pragma unroll
    for (int q = 0; q < 8; q++) {
        if (MODE == 1)      bv[q] = __ldg(bias + cg * 8 + q);
        else if (cg >= 8)   bv[q] = __ldg(bias + (cg - 8) * 8 + q);
        else                bv[q] = 0.f;
    }
    unsigned long long acc[8][4];
    #pragma unroll
    for (int j = 0; j < 8; j++) {
        acc[j][0] = pk2(bv[0], bv[1]);
        acc[j][1] = pk2(bv[2], bv[3]);
        acc[j][2] = pk2(bv[4], bv[5]);
        acc[j][3] = pk2(bv[6], bv[7]);
    }

    // ---- K chunks of 64 ----
    for (int c = 0; c < 2; c++) {
        __syncthreads();             // protect As from previous chunk's readers
        // stage A chunk: 2048 float4, i -> k4 = i&15, node = i>>4
        #pragma unroll
        for (int m = 0; m < 8; m++) {
            int i = tid + 256 * m;
            int k4 = i & 15, node = i >> 4;
            int gnode = nodeB + node;
            float4 v = make_float4(0.f, 0.f, 0.f, 0.f);
            if (gnode < NND) {
                if (MODE == 1) {
                    if (c == 0) {    // k 0..63 : mean = agg1 * rinv
                        v = *((const float4*)g_agg1 + (size_t)gnode * 16 + k4);
                        int cn = g_cnt[gnode];
                        float ri = 1.f / (float)(cn < 1 ? 1 : cn);
                        v.x *= ri; v.y *= ri; v.z *= ri; v.w *= ri;
                        if (k4 == 0) g_rinv[gnode] = ri;
                    } else {         // k 64..127 : x
                        v = __ldg((const float4*)xin + (size_t)gnode * 16 + k4);
                    }
                } else {
                    v = *((const float4*)g_h + (size_t)gnode * 32 + c * 16 + k4);
                }
            }
            ((float4*)As)[node * 17 + k4] = v;
        }
        __syncthreads();

        // compute 16 k4 groups of this chunk
        for (int k4 = 0; k4 < 16; k4++) {
            float4 av[8];
            #pragma unroll
            for (int j = 0; j < 8; j++)
                av[j] = ((const float4*)As)[(ng + 16 * j) * 17 + k4];
            #pragma unroll
            for (int kk = 0; kk < 4; kk++) {
                const float* wrow = Ws + (c * 64 + k4 * 4 + kk) * 128 + cg * 8;
                float4 w0 = *(const float4*)(wrow);
                float4 w1 = *(const float4*)(wrow + 4);
                unsigned long long w01 = pk2(w0.x, w0.y);
                unsigned long long w23 = pk2(w0.z, w0.w);
                unsigned long long w45 = pk2(w1.x, w1.y);
                unsigned long long w67 = pk2(w1.z, w1.w);
                #pragma unroll
                for (int j = 0; j < 8; j++) {
                    float a = (kk == 0) ? av[j].x : (kk == 1) ? av[j].y
                            : (kk == 2) ? av[j].z : av[j].w;
                    unsigned long long aa = pk2(a, a);
                    FMA2(acc[j][0], aa, w01);
                    FMA2(acc[j][1], aa, w23);
                    FMA2(acc[j][2], aa, w45);
                    FMA2(acc[j][3], aa, w67);
                }
            }
        }
    }

    // ---- write out ----
    #pragma unroll
    for (int j = 0; j < 8; j++) {
        int node = nodeB + ng + 16 * j;
        if (node < NND) {
            float f0,f1,f2,f3,f4,f5,f6,f7;
            upk2(f0, f1, acc[j][0]);
            upk2(f2, f3, acc[j][1]);
            upk2(f4, f5, acc[j][2]);
            upk2(f6, f7, acc[j][3]);
            if (MODE == 1) {
                float* dp = g_h + (size_t)node * 128 + cg * 8;
                *(float4*)(dp)     = make_float4(fmaxf(f0,0.f), fmaxf(f1,0.f),
                                                 fmaxf(f2,0.f), fmaxf(f3,0.f));
                *(float4*)(dp + 4) = make_float4(fmaxf(f4,0.f), fmaxf(f5,0.f),
                                                 fmaxf(f6,0.f), fmaxf(f7,0.f));
            } else {
                float* dst = (cg < 8) ? (g_p + (size_t)node * 64 + cg * 8)
                                      : (outr + (size_t)node * 64 + (cg - 8) * 8);
                *(float4*)(dst)     = make_float4(f0, f1, f2, f3);
                *(float4*)(dst + 4) = make_float4(f4, f5, f6, f7);
            }
        }
    }
}

// ---------------- finalize: out += agg2 * rinv ----------------
__global__ void k_final(float* __restrict__ out) {
    int t = blockIdx.x * 256 + threadIdx.x;     // exactly NND*16 = 1.6M threads
    int node = t >> 4;
    float ri = g_rinv[node];
    float4 a = ((const float4*)g_agg2)[t];
    float4 o = ((float4*)out)[t];
    o.x = fmaf(a.x, ri, o.x);
    o.y = fmaf(a.y, ri, o.y);
    o.z = fmaf(a.z, ri, o.z);
    o.w = fmaf(a.w, ri, o.w);
    ((float4*)out)[t] = o;
}

// ---------------- launch ----------------
extern "C" void kernel_launch(void* const* d_in, const int* in_sizes, int n_in,
                              void* d_out, int out_size) {
    const float* x   = nullptr;
    const float* b1  = nullptr;
    const float* b2  = nullptr;
    const int*   ei  = nullptr;
    const float* W[4] = {nullptr, nullptr, nullptr, nullptr};
    int wn = 0;
    for (int i = 0; i < n_in; i++) {
        int sz = in_sizes[i];
        if      (sz == NND * 64)  x  = (const float*)d_in[i];
        else if (sz == 2 * NE)    ei = (const int*)d_in[i];
        else if (sz == 128)       b1 = (const float*)d_in[i];
        else if (sz == 64)        b2 = (const float*)d_in[i];
        else if (sz == 8192 && wn < 4) W[wn++] = (const float*)d_in[i];
    }
    const float* W1l = W[0];
    const float* W1r = W[1];
    const float* W2l = W[2];
    const float* W2r = W[3];
    float* out = (float*)d_out;

    const int SMG = 16384 * 4 + 128 * 17 * 16;   // 64KB W + 34KB A = 100352 B
    cudaFuncSetAttribute(k_gemm<1>, cudaFuncAttributeMaxDynamicSharedMemorySize, SMG);
    cudaFuncSetAttribute(k_gemm<2>, cudaFuncAttributeMaxDynamicSharedMemorySize, SMG);

    int gemm_blocks = (NND + 127) / 128;         // 782

    k_init<<<25000, 256>>>(ei);                  // NND*64 threads
    k_scatter<1><<<62500, 256>>>(x);             // NE*16 threads, also counts degrees
    k_gemm<1><<<gemm_blocks, 256, SMG>>>(x, W1l, W1r, b1, nullptr);
    k_gemm<2><<<gemm_blocks, 256, SMG>>>(nullptr, W2l, W2r, b2, out);
    k_scatter<2><<<62500, 256>>>(nullptr);       // p -> agg2
    k_final<<<6250, 256>>>(out);                 // NND*16 threads
}